// round 5
// baseline (speedup 1.0000x reference)
#include <cuda_runtime.h>

// ---------------------------------------------------------------------------
// VectorQuantizer on GB300 — round 4: 8x8 tile, row-paired f32x2 accumulators,
// no smem data duplication (1 byte of LDS return per FMA).
// ---------------------------------------------------------------------------

#define SXROW 68     // 64 rows + pad
#define SEROW 132    // 128 codes + pad

static const long long Q_OFF     = 0LL;
static const long long LOSS_OFF  = 4194304LL;
static const long long PERP_OFF  = 4194305LL;
static const long long ENC_OFF   = 4194306LL;
static const long long INDS_OFF  = 71303170LL;
static const long long DIST_OFF  = 71368706LL;
static const long long TOTAL_OUT = 138477570LL;

__device__ int          g_inds[65536];
__device__ float        g_msep[1024];
__device__ unsigned int g_ticket;   // monotonic across replays

#define FMA2(d, a, b, c) \
    asm("fma.rn.f32x2 %0, %1, %2, %3;" : "=l"(d) : "l"(a), "l"(b), "l"(c))
#define DUPF(d, f) \
    asm("mov.b64 %0, {%1, %1};" : "=l"(d) : "r"(__float_as_uint(f)))

__device__ __forceinline__ float2 unpack2(unsigned long long v) {
    unsigned int lo, hi;
    asm("mov.b64 {%0, %1}, %2;" : "=r"(lo), "=r"(hi) : "l"(v));
    return make_float2(__uint_as_float(lo), __uint_as_float(hi));
}

// smem float offsets
#define SX_OFF   0        // 64*68  = 4352
#define SE_OFF   4352     // 64*132 = 8448
#define SCQ_OFF  12800    // 128
#define XSQ_OFF  12928    // 64
#define SPK_OFF  12992    // 64 u64 (128 floats)
#define SIND_OFF 13120    // 64
#define SRED_OFF 13184    // 16
#define SFLG_OFF 13200    // 1
#define SMEMF    13204

template <bool FULL>
__global__ void __launch_bounds__(128, 4)
vq_fused(const float* __restrict__ lat, const float* __restrict__ emb,
         float* __restrict__ out) {
    extern __shared__ float sm[];
    float* sx  = sm + SX_OFF;
    float* se  = sm + SE_OFF;
    float* scq = sm + SCQ_OFF;
    float* xsq = sm + XSQ_OFF;
    unsigned long long* spk = (unsigned long long*)(sm + SPK_OFF);
    int*   sind = (int*)(sm + SIND_OFF);
    float* sred = sm + SRED_OFF;
    int*   sflg = (int*)(sm + SFLG_OFF);

    const int tid = threadIdx.x;
    const int n0  = blockIdx.x * 64;    // 64 rows per block
    const int b   = n0 >> 12;
    const int hw0 = n0 & 4095;
    const int ty  = tid >> 4;            // 0..7: rows ty*8..+7
    const int tx  = tid & 15;            // 8 codes per 128-code chunk

    // ---- x tile: sx[d][r] ----
    {
        const float4* lat4 = (const float4*)lat;
        #pragma unroll
        for (int i = 0; i < 8; ++i) {
            int idx = tid + i * 128;          // 1024 float4
            int d = idx >> 4, q = idx & 15;
            float4 v = lat4[b * 65536 + d * 1024 + (hw0 >> 2) + q];
            *(float4*)(sx + d * SXROW + q * 4) = v;
        }
    }
    if (tid < 64) spk[tid] = 0xFFFFFFFFFFFFFFFFULL;
    __syncthreads();
    if (tid < 64) {
        float s = 0.f;
        #pragma unroll
        for (int d = 0; d < 64; ++d) { float v = sx[d * SXROW + tid]; s += v * v; }
        xsq[tid] = s;
    }

    float bv[8]; int bi[8];
    #pragma unroll
    for (int r = 0; r < 8; ++r) { bv[r] = 3.4e38f; bi[r] = 0; }

    for (int chunk = 0; chunk < 8; ++chunk) {
        __syncthreads();   // A: se/scq reuse safe, xsq/spk ready first iter
        // gmem -> smem transpose, 16B-block XOR swizzle by dq
        const float4* src = (const float4*)emb + chunk * 2048;
        #pragma unroll
        for (int i = 0; i < 16; ++i) {
            int fidx = tid + i * 128;          // 128 codes x 16 d-quads
            int k = fidx >> 4, dq = fidx & 15;
            float4 v = src[fidx];
            float* p = se + dq * 4 * SEROW + (((k >> 2) ^ dq) << 2) + (k & 3);
            p[0]         = v.x;
            p[SEROW]     = v.y;
            p[2 * SEROW] = v.z;
            p[3 * SEROW] = v.w;
        }
        __syncthreads();   // B

        // ||e||^2 for the chunk's 128 codes (one code per thread)
        {
            int cb = tid >> 2, cl = tid & 3;
            float s = 0.f;
            #pragma unroll
            for (int dq = 0; dq < 16; ++dq) {
                const float* p = se + dq * 4 * SEROW + ((cb ^ dq) << 2) + cl;
                float a0 = p[0], a1 = p[SEROW], a2 = p[2 * SEROW], a3 = p[3 * SEROW];
                s += a0 * a0 + a1 * a1 + a2 * a2 + a3 * a3;
            }
            scq[tid] = s;
        }

        // ---- main: 8 rows (4 f32x2 pairs) x 8 codes ----
        unsigned long long acc[4][8];
        #pragma unroll
        for (int p = 0; p < 4; ++p)
            #pragma unroll
            for (int c = 0; c < 8; ++c) acc[p][c] = 0ULL;

        #pragma unroll 1
        for (int dq = 0; dq < 16; ++dq) {
            const int b0 = (((tx << 1)    ) ^ dq) << 2;
            const int b1 = (((tx << 1) + 1) ^ dq) << 2;
            #pragma unroll
            for (int j = 0; j < 4; ++j) {
                const int d = (dq << 2) + j;
                const float* xr = sx + d * SXROW + (ty << 3);
                const float* er = se + d * SEROW;
                ulonglong2 xa = *(const ulonglong2*)xr;        // rows 0-3 (2 pairs)
                ulonglong2 xb = *(const ulonglong2*)(xr + 4);  // rows 4-7
                float4 ea = *(const float4*)(er + b0);         // codes 0-3
                float4 eb = *(const float4*)(er + b1);         // codes 4-7
                unsigned long long ed0, ed1;
                DUPF(ed0, ea.x);
                FMA2(acc[0][0], xa.x, ed0, acc[0][0]);
                FMA2(acc[1][0], xa.y, ed0, acc[1][0]);
                FMA2(acc[2][0], xb.x, ed0, acc[2][0]);
                FMA2(acc[3][0], xb.y, ed0, acc[3][0]);
                DUPF(ed1, ea.y);
                FMA2(acc[0][1], xa.x, ed1, acc[0][1]);
                FMA2(acc[1][1], xa.y, ed1, acc[1][1]);
                FMA2(acc[2][1], xb.x, ed1, acc[2][1]);
                FMA2(acc[3][1], xb.y, ed1, acc[3][1]);
                DUPF(ed0, ea.z);
                FMA2(acc[0][2], xa.x, ed0, acc[0][2]);
                FMA2(acc[1][2], xa.y, ed0, acc[1][2]);
                FMA2(acc[2][2], xb.x, ed0, acc[2][2]);
                FMA2(acc[3][2], xb.y, ed0, acc[3][2]);
                DUPF(ed1, ea.w);
                FMA2(acc[0][3], xa.x, ed1, acc[0][3]);
                FMA2(acc[1][3], xa.y, ed1, acc[1][3]);
                FMA2(acc[2][3], xb.x, ed1, acc[2][3]);
                FMA2(acc[3][3], xb.y, ed1, acc[3][3]);
                DUPF(ed0, eb.x);
                FMA2(acc[0][4], xa.x, ed0, acc[0][4]);
                FMA2(acc[1][4], xa.y, ed0, acc[1][4]);
                FMA2(acc[2][4], xb.x, ed0, acc[2][4]);
                FMA2(acc[3][4], xb.y, ed0, acc[3][4]);
                DUPF(ed1, eb.y);
                FMA2(acc[0][5], xa.x, ed1, acc[0][5]);
                FMA2(acc[1][5], xa.y, ed1, acc[1][5]);
                FMA2(acc[2][5], xb.x, ed1, acc[2][5]);
                FMA2(acc[3][5], xb.y, ed1, acc[3][5]);
                DUPF(ed0, eb.z);
                FMA2(acc[0][6], xa.x, ed0, acc[0][6]);
                FMA2(acc[1][6], xa.y, ed0, acc[1][6]);
                FMA2(acc[2][6], xb.x, ed0, acc[2][6]);
                FMA2(acc[3][6], xb.y, ed0, acc[3][6]);
                DUPF(ed1, eb.w);
                FMA2(acc[0][7], xa.x, ed1, acc[0][7]);
                FMA2(acc[1][7], xa.y, ed1, acc[1][7]);
                FMA2(acc[2][7], xb.x, ed1, acc[2][7]);
                FMA2(acc[3][7], xb.y, ed1, acc[3][7]);
            }
        }
        __syncthreads();   // C: scq visible to all

        // ---- epilogue ----
        const int cbase = (chunk << 7) + (tx << 3);
        float4 qa = *(const float4*)(scq + (tx << 3));
        float4 qb = *(const float4*)(scq + (tx << 3) + 4);
        float eq[8] = {qa.x, qa.y, qa.z, qa.w, qb.x, qb.y, qb.z, qb.w};
        #pragma unroll
        for (int p = 0; p < 4; ++p) {
            const int r0 = (ty << 3) + (p << 1);
            const float xs0 = xsq[r0], xs1 = xsq[r0 + 1];
            float dd0[8], dd1[8];
            #pragma unroll
            for (int c = 0; c < 8; ++c) {
                float2 pr = unpack2(acc[p][c]);
                dd0[c] = fmaf(-2.f, pr.x, xs0 + eq[c]);
                dd1[c] = fmaf(-2.f, pr.y, xs1 + eq[c]);
                if (dd0[c] < bv[2 * p])     { bv[2 * p]     = dd0[c]; bi[2 * p]     = cbase + c; }
                if (dd1[c] < bv[2 * p + 1]) { bv[2 * p + 1] = dd1[c]; bi[2 * p + 1] = cbase + c; }
            }
            if (FULL) {
                long long nr = n0 + r0;
                float* dp = out + DIST_OFF + nr * 1024 + cbase;
                float* ep = out + ENC_OFF  + nr * 1024 + cbase;
                __stcs((float2*)(dp),        make_float2(dd0[0], dd0[1]));
                __stcs((float2*)(dp + 2),    make_float2(dd0[2], dd0[3]));
                __stcs((float2*)(dp + 4),    make_float2(dd0[4], dd0[5]));
                __stcs((float2*)(dp + 6),    make_float2(dd0[6], dd0[7]));
                __stcs((float2*)(dp + 1024), make_float2(dd1[0], dd1[1]));
                __stcs((float2*)(dp + 1026), make_float2(dd1[2], dd1[3]));
                __stcs((float2*)(dp + 1028), make_float2(dd1[4], dd1[5]));
                __stcs((float2*)(dp + 1030), make_float2(dd1[6], dd1[7]));
                const float2 z = make_float2(0.f, 0.f);
                __stcs((float2*)(ep),        z);
                __stcs((float2*)(ep + 2),    z);
                __stcs((float2*)(ep + 4),    z);
                __stcs((float2*)(ep + 6),    z);
                __stcs((float2*)(ep + 1024), z);
                __stcs((float2*)(ep + 1026), z);
                __stcs((float2*)(ep + 1028), z);
                __stcs((float2*)(ep + 1030), z);
            }
        }
    }

    // ---- per-row argmin across tx threads ----
    #pragma unroll
    for (int r = 0; r < 8; ++r) {
        unsigned long long pk =
            ((unsigned long long)__float_as_uint(bv[r]) << 32) | (unsigned)bi[r];
        atomicMin(&spk[(ty << 3) + r], pk);
    }
    __syncthreads();

    if (tid < 64) {
        unsigned long long pk = spk[tid];
        int   ii = (int)(unsigned)(pk & 0xFFFFFFFFULL);
        float mv = __uint_as_float((unsigned)(pk >> 32));
        sind[tid] = ii;
        g_inds[n0 + tid] = ii;
        if (FULL) {
            out[INDS_OFF + n0 + tid] = (float)ii;
            out[ENC_OFF + (long long)(n0 + tid) * 1024 + ii] = 1.0f;
        }
        float s = mv;
        #pragma unroll
        for (int o = 16; o > 0; o >>= 1)
            s += __shfl_down_sync(0xffffffffu, s, o);
        if ((tid & 31) == 0) sred[tid >> 5] = s;
    }
    __syncthreads();
    if (tid == 0) g_msep[blockIdx.x] = sred[0] + sred[1];

    // ---- quantize gather (coalesced over r) ----
    #pragma unroll
    for (int i = 0; i < 32; ++i) {
        int idx = tid + i * 128;
        int r = idx & 63, d = idx >> 6;
        out[Q_OFF + (long long)b * 262144 + d * 4096 + hw0 + r] =
            __ldg(emb + sind[r] * 64 + d);
    }

    // ---- last-block finalize ----
    __syncthreads();
    if (tid == 0) {
        __threadfence();
        unsigned old = atomicAdd(&g_ticket, 1u);
        sflg[0] = ((old & 1023u) == 1023u) ? 1 : 0;
    }
    __syncthreads();
    if (sflg[0]) {
        __threadfence();
        int* hist = (int*)sm;   // reuse sx region
        #pragma unroll
        for (int i = 0; i < 8; ++i) hist[tid + i * 128] = 0;
        __syncthreads();
        #pragma unroll 4
        for (int i = 0; i < 512; ++i)
            atomicAdd(&hist[g_inds[i * 128 + tid]], 1);
        __syncthreads();
        float ent = 0.f, msel = 0.f;
        #pragma unroll
        for (int i = 0; i < 8; ++i) {
            float p = (float)hist[tid + i * 128] * (1.0f / 65536.0f);
            ent  += p * logf(p + 1e-10f);
            msel += g_msep[tid + i * 128];
        }
        #pragma unroll
        for (int o = 16; o > 0; o >>= 1) {
            ent  += __shfl_down_sync(0xffffffffu, ent,  o);
            msel += __shfl_down_sync(0xffffffffu, msel, o);
        }
        if ((tid & 31) == 0) { sred[tid >> 5] = ent; sred[4 + (tid >> 5)] = msel; }
        __syncthreads();
        if (tid == 0 && FULL) {
            float e = sred[0] + sred[1] + sred[2] + sred[3];
            float m = sred[4] + sred[5] + sred[6] + sred[7];
            out[PERP_OFF] = expf(-e);
            out[LOSS_OFF] = m * (1.25f / (65536.0f * 64.0f));
        }
    }
}

// ---------------------------------------------------------------------------
extern "C" void kernel_launch(void* const* d_in, const int* in_sizes, int n_in,
                              void* d_out, int out_size) {
    const float* lat = (const float*)d_in[0];
    const float* emb = (const float*)d_in[1];
    if (n_in >= 2 && in_sizes[0] == 1024 * 64 && in_sizes[1] == 65536 * 64) {
        lat = (const float*)d_in[1];
        emb = (const float*)d_in[0];
    }
    float* out = (float*)d_out;
    const bool full = ((long long)out_size >= TOTAL_OUT);
    const int smem_bytes = SMEMF * 4;   // 52816

    static int cfg = 0;
    if (!cfg) {
        cudaFuncSetAttribute(vq_fused<true>,
                             cudaFuncAttributeMaxDynamicSharedMemorySize, smem_bytes);
        cudaFuncSetAttribute(vq_fused<false>,
                             cudaFuncAttributeMaxDynamicSharedMemorySize, smem_bytes);
        cfg = 1;
    }
    if (full) vq_fused<true><<<1024, 128, smem_bytes>>>(lat, emb, out);
    else      vq_fused<false><<<1024, 128, smem_bytes>>>(lat, emb, out);
}